// round 12
// baseline (speedup 1.0000x reference)
#include <cuda_runtime.h>
#include <cuda_bf16.h>
#include <math.h>
#include <stdint.h>

#define W_ 152
#define H_ 100
#define NPIX 15200
#define KTOT 4608
#define NANCH 136800
#define NCAND 8192
#define NHIST 4096
#define PRE_NMS_N 6000
#define POST_NMS_N 300
#define MASK_W 94
#define NITH 288                // HMMA iters (BK=16)
#define NITF 576                // FFMA iters (BK=8)
#define PITCH 80
#define A_TILE 5120             // 64 m-rows * 80B (HMMA A)
#define B_TILE 10240            // 128 n-rows * 80B (HMMA B)
#define HSTAGE (3 * A_TILE + 3 * B_TILE)   // 46080
#define HSMEM (2 * HSTAGE)                 // 92160
#define FA_B 2176               // 8k x 68 floats
#define FB_B 4224               // 8k x 132 floats
#define SMEM_DYN (HSMEM + 2 * FA_B + 2 * FB_B)  // 104960

__device__ float g_wT[512 * KTOT];
__device__ __nv_bfloat16 g_wa_hi[512 * KTOT];
__device__ __nv_bfloat16 g_wa_mid[512 * KTOT];
__device__ __nv_bfloat16 g_wa_lo[512 * KTOT];
__device__ __nv_bfloat16 g_in_hi[NPIX * 512];
__device__ __nv_bfloat16 g_in_mid[NPIX * 512];
__device__ __nv_bfloat16 g_in_lo[NPIX * 512];
__device__ float g_x[512 * NPIX];
__device__ float g_head[54 * NPIX];
__device__ float4 g_boxes[NANCH];
__device__ unsigned long long g_keys[NANCH];
__device__ unsigned long long g_cand[NCAND];
__device__ int g_hist1[NHIST];
__device__ int g_hist2[NHIST];
__device__ int g_b1;
__device__ int g_above1;
__device__ unsigned g_T24;
__device__ int g_count;
__device__ float4 g_top_boxes[PRE_NMS_N];
__device__ unsigned long long g_mask[(size_t)PRE_NMS_N * MASK_W];
__device__ int g_sel[POST_NMS_N];

__constant__ float c_anchors[9][4] = {
    {-84.f,-40.f,99.f,55.f},{-176.f,-88.f,191.f,103.f},{-360.f,-184.f,375.f,199.f},
    {-56.f,-56.f,71.f,71.f},{-120.f,-120.f,135.f,135.f},{-248.f,-248.f,263.f,263.f},
    {-36.f,-80.f,51.f,95.f},{-80.f,-168.f,95.f,183.f},{-168.f,-344.f,183.f,359.f}
};

__device__ __forceinline__ uint32_t smem_u32(const void* p) {
    uint32_t a;
    asm("{ .reg .u64 t; cvta.to.shared.u64 t, %1; cvt.u32.u64 %0, t; }" : "=r"(a) : "l"(p));
    return a;
}
#define LDSMX4(d, addr) \
    asm volatile("ldmatrix.sync.aligned.m8n8.x4.shared.b16 {%0,%1,%2,%3}, [%4];" \
        : "=r"((d)[0]), "=r"((d)[1]), "=r"((d)[2]), "=r"((d)[3]) : "r"(addr))
#define MMA16816(c, a, b0, b1) \
    asm volatile("mma.sync.aligned.m16n8k16.row.col.f32.bf16.bf16.f32 " \
        "{%0,%1,%2,%3}, {%4,%5,%6,%7}, {%8,%9}, {%0,%1,%2,%3};" \
        : "+f"((c)[0]), "+f"((c)[1]), "+f"((c)[2]), "+f"((c)[3]) \
        : "r"((a)[0]), "r"((a)[1]), "r"((a)[2]), "r"((a)[3]), "r"(b0), "r"(b1))
#define BAR_H() asm volatile("bar.sync 1, 256;" ::: "memory")
#define BAR_F() asm volatile("bar.sync 2, 128;" ::: "memory")

// ---- weight reorder fp32: g_wT[oc][tap*512+ic]
__global__ __launch_bounds__(256) void wtrans_kernel(const float* __restrict__ wgt)
{
    int idx = blockIdx.x * 256 + threadIdx.x;
    if (idx >= 512 * KTOT) return;
    int oc = idx / KTOT, r = idx - oc * KTOT, tap = r >> 9, ic = r & 511;
    g_wT[idx] = wgt[(size_t)oc * KTOT + ic * 9 + tap];
}

// ---- weight split 3-way bf16
__global__ __launch_bounds__(256) void wsplit_kernel(const float* __restrict__ wgt)
{
    int idx = blockIdx.x * 256 + threadIdx.x;
    if (idx >= 512 * KTOT) return;
    int oc = idx / KTOT, r = idx - oc * KTOT, tap = r >> 9, ic = r & 511;
    float v = wgt[(size_t)oc * KTOT + ic * 9 + tap];
    __nv_bfloat16 h = __float2bfloat16(v);
    float r1 = v - __bfloat162float(h);
    __nv_bfloat16 m = __float2bfloat16(r1);
    __nv_bfloat16 l = __float2bfloat16(r1 - __bfloat162float(m));
    g_wa_hi[idx] = h; g_wa_mid[idx] = m; g_wa_lo[idx] = l;
}

// ---- input transpose+split
__global__ __launch_bounds__(256) void isplit_kernel(const float* __restrict__ in)
{
    __shared__ float t[32][33];
    int p0 = blockIdx.x * 32, ic0 = blockIdx.y * 32;
    int tx = threadIdx.x & 31, ty = threadIdx.x >> 5;
#pragma unroll
    for (int r = 0; r < 4; r++)
        t[ty + 8 * r][tx] = in[(size_t)(ic0 + ty + 8 * r) * NPIX + p0 + tx];
    __syncthreads();
#pragma unroll
    for (int r = 0; r < 4; r++) {
        int pl = ty + 8 * r;
        float v = t[tx][pl];
        __nv_bfloat16 h = __float2bfloat16(v);
        float r1 = v - __bfloat162float(h);
        __nv_bfloat16 m = __float2bfloat16(r1);
        __nv_bfloat16 l = __float2bfloat16(r1 - __bfloat162float(m));
        size_t o = (size_t)(p0 + pl) * 512 + ic0 + tx;
        g_in_hi[o] = h; g_in_mid[o] = m; g_in_lo[o] = l;
    }
}

// ---- hybrid conv (m-split): warps 0-7 HMMA m[bm,bm+64) (R10 chain),
//                             warps 8-11 FFMA2 m[bm+64,bm+128) (R3 chain)
__global__ __launch_bounds__(384, 1) void conv_hybrid_kernel(
    const float* __restrict__ in, const float* __restrict__ conv_b)
{
    extern __shared__ char sm[];
    const int tid = threadIdx.x;
    const int bn = blockIdx.x * 128, bm = blockIdx.y * 128;

    if (tid < 256) {
        // ================= HMMA group: m in [bm, bm+64), n full 128 =================
        const uint32_t sb = smem_u32(sm);
        const int l = tid & 31, wid = tid >> 5;
        const int wm = wid >> 2, wn = wid & 3;   // warp tile 32m x 32n

        // loaders: A by tid<128 (64 rows x 2 halves); B by all 256 (128 rows x 2 halves)
        const bool doA = (tid < 128);
        const int rA = tid >> 1, hA = tid & 1;
        const size_t abase = (size_t)(bm + rA) * KTOT + hA * 8;
        const uint32_t sts_offA = rA * PITCH + hA * 16;
        const int rB = tid >> 1, hB = tid & 1;
        const int pB = bn + rB;
        const bool pvB = (pB < NPIX);
        const int h0 = pvB ? pB / W_ : 0;
        const int w0 = pB - h0 * W_;
        const size_t bbase = (size_t)pB * 512 + hB * 8;
        const uint32_t sts_offB = rB * PITCH + hB * 16;

        const uint32_t alane = (l & 15) * PITCH + (l >> 4) * 16;
        const uint32_t blane = ((l & 7) + ((l >> 4) & 1) * 8) * PITCH + ((l >> 3) & 1) * 16;

        float accM[2][4][4], accS[2][4][4];
#pragma unroll
        for (int i = 0; i < 2; i++)
#pragma unroll
            for (int j = 0; j < 4; j++)
#pragma unroll
                for (int q = 0; q < 4; q++) { accM[i][j][q] = 0.f; accS[i][j][q] = 0.f; }

        uint4 av[3], bv[3];
        auto gload = [&](int it) {
            int k0 = (NITH - 1 - it) * 16;     // reversed, as R10
            int tap = k0 >> 9, icc = k0 & 511;
            int ty3 = tap / 3, dy = ty3 - 1, dx = tap - ty3 * 3 - 1;
            if (doA) {
                size_t ao = (abase + tap * 512 + icc) >> 3;
                av[0] = ((const uint4*)g_wa_hi)[ao];
                av[1] = ((const uint4*)g_wa_mid)[ao];
                av[2] = ((const uint4*)g_wa_lo)[ao];
            }
            int hh = h0 + dy, ww = w0 + dx;
            uint4 z = make_uint4(0, 0, 0, 0);
            bv[0] = z; bv[1] = z; bv[2] = z;
            if (pvB && hh >= 0 && hh < H_ && ww >= 0 && ww < W_) {
                size_t bo = ((size_t)((long)bbase + (long)(dy * W_ + dx) * 512 + icc)) >> 3;
                bv[0] = ((const uint4*)g_in_hi)[bo];
                bv[1] = ((const uint4*)g_in_mid)[bo];
                bv[2] = ((const uint4*)g_in_lo)[bo];
            }
        };
        auto sts = [&](int stg) {
            char* st = sm + stg * HSTAGE;
            if (doA) {
                *(uint4*)(st + 0 * A_TILE + sts_offA) = av[0];
                *(uint4*)(st + 1 * A_TILE + sts_offA) = av[1];
                *(uint4*)(st + 2 * A_TILE + sts_offA) = av[2];
            }
            *(uint4*)(st + 3 * A_TILE + 0 * B_TILE + sts_offB) = bv[0];
            *(uint4*)(st + 3 * A_TILE + 1 * B_TILE + sts_offB) = bv[1];
            *(uint4*)(st + 3 * A_TILE + 2 * B_TILE + sts_offB) = bv[2];
        };

        gload(0);
        sts(0);
        BAR_H();

        const int pav[6] = {1, 1, 2, 0, 0, 0};
        const int pbv[6] = {1, 0, 0, 2, 1, 0};

        for (int it = 0; it < NITH; it++) {
            if (it + 1 < NITH) gload(it + 1);

            const uint32_t s0 = sb + (it & 1) * HSTAGE;
            const uint32_t aT = s0 + (wm * 32) * PITCH + alane;
            const uint32_t bT = s0 + 3 * A_TILE + (wn * 32) * PITCH + blane;
            uint32_t af[2][4];
#pragma unroll
            for (int pp = 0; pp < 6; pp++) {
                const int va = pav[pp], vb = pbv[pp];
                if (pp == 0 || va != pav[pp - 1]) {
#pragma unroll
                    for (int mt = 0; mt < 2; mt++)
                        LDSMX4(af[mt], aT + va * A_TILE + mt * 16 * PITCH);
                }
                uint32_t t0[4], t1[4];
                LDSMX4(t0, bT + vb * B_TILE);
                LDSMX4(t1, bT + vb * B_TILE + 16 * PITCH);
                if (pp < 5) {
#pragma unroll
                    for (int mt = 0; mt < 2; mt++) {
                        MMA16816(accS[mt][0], af[mt], t0[0], t0[1]);
                        MMA16816(accS[mt][1], af[mt], t0[2], t0[3]);
                        MMA16816(accS[mt][2], af[mt], t1[0], t1[1]);
                        MMA16816(accS[mt][3], af[mt], t1[2], t1[3]);
                    }
                } else {
#pragma unroll
                    for (int mt = 0; mt < 2; mt++) {
                        MMA16816(accM[mt][0], af[mt], t0[0], t0[1]);
                        MMA16816(accM[mt][1], af[mt], t0[2], t0[3]);
                        MMA16816(accM[mt][2], af[mt], t1[0], t1[1]);
                        MMA16816(accM[mt][3], af[mt], t1[2], t1[3]);
                    }
                }
            }

            if (it + 1 < NITH) sts((it + 1) & 1);
            BAR_H();
        }

        const int g = l >> 2, t4 = l & 3;
#pragma unroll
        for (int mt = 0; mt < 2; mt++) {
            int m0 = bm + wm * 32 + mt * 16 + g;
            float b0v = conv_b[m0], b1v = conv_b[m0 + 8];
#pragma unroll
            for (int nt = 0; nt < 4; nt++) {
                int n = bn + wn * 32 + nt * 8 + t4 * 2;
                if (n < NPIX) {
                    float s0v = __fadd_rn(accM[mt][nt][0], accS[mt][nt][0]);
                    float s1v = __fadd_rn(accM[mt][nt][1], accS[mt][nt][1]);
                    float s2v = __fadd_rn(accM[mt][nt][2], accS[mt][nt][2]);
                    float s3v = __fadd_rn(accM[mt][nt][3], accS[mt][nt][3]);
                    float2 v0, v1;
                    v0.x = fmaxf(__fadd_rn(s0v, b0v), 0.f);
                    v0.y = fmaxf(__fadd_rn(s1v, b0v), 0.f);
                    v1.x = fmaxf(__fadd_rn(s2v, b1v), 0.f);
                    v1.y = fmaxf(__fadd_rn(s3v, b1v), 0.f);
                    *(float2*)&g_x[(size_t)m0 * NPIX + n] = v0;
                    *(float2*)&g_x[(size_t)(m0 + 8) * NPIX + n] = v1;
                }
            }
        }
    } else {
        // ============ FFMA2 group: m in [bm+64, bm+128), n full 128, R3 chain ============
        const int ft = tid - 256;            // 0..127
        float* FA0 = (float*)(sm + HSMEM);
        float* FA1 = (float*)(sm + HSMEM + FA_B);
        float* FB0 = (float*)(sm + HSMEM + 2 * FA_B);
        float* FB1 = (float*)(sm + HSMEM + 2 * FA_B + FB_B);
        const int tx = ft & 15, ty = ft >> 4;   // 16 n-groups x 8 m-groups
        const int bmF = bm + 64;

        const int mA = ft >> 1;                 // 0..63
        const int kqA = (ft & 1) * 4;
        int kkB[8], nnB[8], pBf[8], hBf[8], wBf[8];
        bool pvBf[8];
#pragma unroll
        for (int rr = 0; rr < 8; rr++) {
            int e = rr * 128 + ft;
            kkB[rr] = e >> 7;
            nnB[rr] = e & 127;
            pBf[rr] = bn + nnB[rr];
            pvBf[rr] = pBf[rr] < NPIX;
            hBf[rr] = pvBf[rr] ? pBf[rr] / W_ : 0;
            wBf[rr] = pBf[rr] - hBf[rr] * W_;
        }

        unsigned long long acc[8][4];
#pragma unroll
        for (int i = 0; i < 8; i++)
#pragma unroll
            for (int j = 0; j < 4; j++) acc[i][j] = 0ULL;

        float4 avs;
        float bvs[8];
        auto fload = [&](int it) {
            int k0 = it * 8;                   // forward, as R3
            int tap = k0 >> 9, ic0 = k0 & 511;
            int ty3 = tap / 3, dy = ty3 - 1, dx = tap - ty3 * 3 - 1;
            avs = *reinterpret_cast<const float4*>(
                g_wT + (size_t)(bmF + mA) * KTOT + k0 + kqA);
#pragma unroll
            for (int rr = 0; rr < 8; rr++) {
                int hh = hBf[rr] + dy, ww = wBf[rr] + dx;
                bool v = pvBf[rr] && hh >= 0 && hh < H_ && ww >= 0 && ww < W_;
                bvs[rr] = v ? __ldg(in + (size_t)(ic0 + kkB[rr]) * NPIX + pBf[rr] + dy * W_ + dx)
                            : 0.f;
            }
        };
        auto fsts = [&](int buf) {
            float* As = buf ? FA1 : FA0;
            float* Bs = buf ? FB1 : FB0;
            As[(kqA + 0) * 68 + mA] = avs.x;
            As[(kqA + 1) * 68 + mA] = avs.y;
            As[(kqA + 2) * 68 + mA] = avs.z;
            As[(kqA + 3) * 68 + mA] = avs.w;
#pragma unroll
            for (int rr = 0; rr < 8; rr++)
                Bs[kkB[rr] * 132 + nnB[rr]] = bvs[rr];
        };

        fload(0);
        fsts(0);
        BAR_F();

        int cur = 0;
        for (int it = 0; it < NITF; it++) {
            bool more = (it + 1 < NITF);
            if (more) fload(it + 1);

            float* As = cur ? FA1 : FA0;
            float* Bs = cur ? FB1 : FB0;
#pragma unroll
            for (int kk = 0; kk < 8; kk++) {
                float4 a0 = *(float4*)&As[kk * 68 + ty * 8];
                float4 a1 = *(float4*)&As[kk * 68 + ty * 8 + 4];
                ulonglong2 bb0 = *(ulonglong2*)&Bs[kk * 132 + tx * 8];
                ulonglong2 bb1 = *(ulonglong2*)&Bs[kk * 132 + tx * 8 + 4];
                unsigned long long b2[4] = {bb0.x, bb0.y, bb1.x, bb1.y};
                float avv[8];
                avv[0]=a0.x; avv[1]=a0.y; avv[2]=a0.z; avv[3]=a0.w;
                avv[4]=a1.x; avv[5]=a1.y; avv[6]=a1.z; avv[7]=a1.w;
                unsigned long long a2[8];
#pragma unroll
                for (int s = 0; s < 8; s++)
                    asm("mov.b64 %0, {%1, %1};" : "=l"(a2[s]) : "f"(avv[s]));
#pragma unroll
                for (int s = 0; s < 8; s++)
#pragma unroll
                    for (int j = 0; j < 4; j++)
                        asm("fma.rn.f32x2 %0, %1, %2, %0;"
                            : "+l"(acc[s][j]) : "l"(a2[s]), "l"(b2[j]));
            }

            if (more) {
                fsts(cur ^ 1);
                BAR_F();
                cur ^= 1;
            }
        }

#pragma unroll
        for (int i = 0; i < 8; i++) {
            int m = bmF + ty * 8 + i;
            float bvv = conv_b[m];
#pragma unroll
            for (int j = 0; j < 4; j++) {
                int n = bn + tx * 8 + j * 2;
                if (n < NPIX) {
                    float lo, hi;
                    asm("mov.b64 {%0, %1}, %2;" : "=f"(lo), "=f"(hi) : "l"(acc[i][j]));
                    lo = fmaxf(__fadd_rn(lo, bvv), 0.f);
                    hi = fmaxf(__fadd_rn(hi, bvv), 0.f);
                    *reinterpret_cast<float2*>(&g_x[(size_t)m * NPIX + n]) =
                        make_float2(lo, hi);
                }
            }
        }
    }
}

// ---- heads: BN=64 (grid 238)
__global__ __launch_bounds__(256) void head_kernel(
    const float* __restrict__ cls_w, const float* __restrict__ cls_b,
    const float* __restrict__ bbox_w, const float* __restrict__ bbox_b)
{
    __shared__ float As[16][68];
    __shared__ float Bs[16][68];
    const int tid = threadIdx.x;
    const int bn = blockIdx.x * 64;
    const int tx = tid & 15, ty = tid >> 4;

    float acc[4][4];
#pragma unroll
    for (int i = 0; i < 4; i++)
#pragma unroll
        for (int j = 0; j < 4; j++) acc[i][j] = 0.f;

    for (int k0 = 0; k0 < 512; k0 += 16) {
        {
            int m = tid >> 2, kq = (tid & 3) << 2;
            float4 v = make_float4(0.f, 0.f, 0.f, 0.f);
            if (m < 18) v = *reinterpret_cast<const float4*>(cls_w + (size_t)m * 512 + k0 + kq);
            else if (m < 54) v = *reinterpret_cast<const float4*>(bbox_w + (size_t)(m - 18) * 512 + k0 + kq);
            As[kq + 0][m] = v.x; As[kq + 1][m] = v.y; As[kq + 2][m] = v.z; As[kq + 3][m] = v.w;
        }
#pragma unroll
        for (int r = 0; r < 4; r++) {
            int e = r * 256 + tid, kk = e >> 6, nn = e & 63, p = bn + nn;
            Bs[kk][nn] = (p < NPIX) ? g_x[(size_t)(k0 + kk) * NPIX + p] : 0.f;
        }
        __syncthreads();
#pragma unroll
        for (int kk = 0; kk < 16; kk++) {
            float a[4], b[4];
            float4 a0 = *reinterpret_cast<float4*>(&As[kk][ty * 4]);
            float4 b0 = *reinterpret_cast<float4*>(&Bs[kk][tx * 4]);
            a[0]=a0.x; a[1]=a0.y; a[2]=a0.z; a[3]=a0.w;
            b[0]=b0.x; b[1]=b0.y; b[2]=b0.z; b[3]=b0.w;
#pragma unroll
            for (int i = 0; i < 4; i++)
#pragma unroll
                for (int j = 0; j < 4; j++)
                    acc[i][j] = __fmaf_rn(a[i], b[j], acc[i][j]);
        }
        __syncthreads();
    }
#pragma unroll
    for (int i = 0; i < 4; i++) {
        int m = ty * 4 + i;
        if (m >= 54) continue;
        float bv = (m < 18) ? cls_b[m] : bbox_b[m - 18];
#pragma unroll
        for (int j = 0; j < 4; j++) {
            int n = bn + tx * 4 + j;
            if (n < NPIX) g_head[(size_t)m * NPIX + n] = __fadd_rn(acc[i][j], bv);
        }
    }
}

__global__ void zero_sel_kernel()
{
    int idx = blockIdx.x * 256 + threadIdx.x;
    if (idx < NCAND) g_cand[idx] = 0ULL;
    if (idx < NHIST) { g_hist1[idx] = 0; g_hist2[idx] = 0; }
    if (idx == 0) g_count = 0;
}

__global__ void decode_kernel(const float* __restrict__ iminfo)
{
    int idx = blockIdx.x * 256 + threadIdx.x;
    if (idx >= NANCH) return;
    int a = idx % 9, p = idx / 9, h = p / W_, w = p - h * W_;

    float s0 = g_head[(size_t)a * NPIX + p];
    float s1 = g_head[(size_t)(9 + a) * NPIX + p];
    float mx = fmaxf(s0, s1);
    float e0 = (float)exp((double)__fsub_rn(s0, mx));
    float e1 = (float)exp((double)__fsub_rn(s1, mx));
    float fg = __fdiv_rn(e1, __fadd_rn(e0, e1));

    float d0 = g_head[(size_t)(18 + a * 4 + 0) * NPIX + p];
    float d1 = g_head[(size_t)(18 + a * 4 + 1) * NPIX + p];
    float d2 = g_head[(size_t)(18 + a * 4 + 2) * NPIX + p];
    float d3 = g_head[(size_t)(18 + a * 4 + 3) * NPIX + p];

    float sx = (float)(w * 16), sy = (float)(h * 16);
    float x1a = c_anchors[a][0] + sx, y1a = c_anchors[a][1] + sy;
    float x2a = c_anchors[a][2] + sx, y2a = c_anchors[a][3] + sy;
    float aw = __fadd_rn(__fsub_rn(x2a, x1a), 1.0f);
    float ah = __fadd_rn(__fsub_rn(y2a, y1a), 1.0f);
    float ax = __fadd_rn(x1a, __fmul_rn(0.5f, aw));
    float ay = __fadd_rn(y1a, __fmul_rn(0.5f, ah));

    float px = __fadd_rn(__fmul_rn(d0, aw), ax);
    float py = __fadd_rn(__fmul_rn(d1, ah), ay);
    float pwv = __fmul_rn((float)exp((double)d2), aw);
    float phv = __fmul_rn((float)exp((double)d3), ah);

    float x1 = __fsub_rn(px, __fmul_rn(0.5f, pwv));
    float y1 = __fsub_rn(py, __fmul_rn(0.5f, phv));
    float x2 = __fadd_rn(px, __fmul_rn(0.5f, pwv));
    float y2 = __fadd_rn(py, __fmul_rn(0.5f, phv));

    float hiX = __fsub_rn(iminfo[1], 1.0f);
    float hiY = __fsub_rn(iminfo[0], 1.0f);
    x1 = fminf(fmaxf(x1, 0.f), hiX);
    y1 = fminf(fmaxf(y1, 0.f), hiY);
    x2 = fminf(fmaxf(x2, 0.f), hiX);
    y2 = fminf(fmaxf(y2, 0.f), hiY);

    float ws = __fadd_rn(__fsub_rn(x2, x1), 1.0f);
    float hs = __fadd_rn(__fsub_rn(y2, y1), 1.0f);
    float msz = __fmul_rn(16.0f, iminfo[2]);
    bool valid = (ws >= msz) && (hs >= msz);
    float score = valid ? fg : -1000000000.0f;

    unsigned u = __float_as_uint(score);
    u = (u & 0x80000000u) ? ~u : (u | 0x80000000u);
    g_keys[idx] = ((unsigned long long)u << 32) | (unsigned)(~(unsigned)idx);
    g_boxes[idx] = make_float4(x1, y1, x2, y2);
    atomicAdd(&g_hist1[u >> 20], 1);
}

__global__ __launch_bounds__(128) void scan1_kernel()
{
    __shared__ int part[128];
    int t = threadIdx.x, s = 0;
#pragma unroll
    for (int q = 0; q < 32; q++) s += g_hist1[t * 32 + q];
    part[t] = s;
    __syncthreads();
    if (t == 0) {
        int cum = 0, seg = 0;
        for (int pp = 127; pp >= 0; pp--) {
            if (cum + part[pp] >= PRE_NMS_N) { seg = pp; break; }
            cum += part[pp];
            if (pp == 0) seg = 0;
        }
        int b = seg * 32 + 31;
        for (; b >= seg * 32; b--) {
            int c = g_hist1[b];
            if (cum + c >= PRE_NMS_N) break;
            cum += c;
        }
        if (b < seg * 32) b = seg * 32;
        g_b1 = b; g_above1 = cum;
    }
}

__global__ void hist2_kernel()
{
    int idx = blockIdx.x * 256 + threadIdx.x;
    if (idx >= NANCH) return;
    unsigned u = (unsigned)(g_keys[idx] >> 32);
    if ((int)(u >> 20) == g_b1) atomicAdd(&g_hist2[(u >> 8) & 0xFFF], 1);
}

__global__ __launch_bounds__(128) void scan2_kernel()
{
    __shared__ int part[128];
    int t = threadIdx.x, s = 0;
#pragma unroll
    for (int q = 0; q < 32; q++) s += g_hist2[t * 32 + q];
    part[t] = s;
    __syncthreads();
    if (t == 0) {
        int cum = g_above1, seg = 0;
        for (int pp = 127; pp >= 0; pp--) {
            if (cum + part[pp] >= PRE_NMS_N) { seg = pp; break; }
            cum += part[pp];
            if (pp == 0) seg = 0;
        }
        int b = seg * 32 + 31;
        for (; b >= seg * 32; b--) {
            int c = g_hist2[b];
            if (cum + c >= PRE_NMS_N) break;
            cum += c;
        }
        if (b < seg * 32) b = seg * 32;
        g_T24 = ((unsigned)g_b1 << 12) | (unsigned)b;
    }
}

__global__ void compact_kernel()
{
    int idx = blockIdx.x * 256 + threadIdx.x;
    if (idx >= NANCH) return;
    unsigned long long key = g_keys[idx];
    unsigned u = (unsigned)(key >> 32);
    if ((u >> 8) >= g_T24) {
        int pos = atomicAdd(&g_count, 1);
        if (pos < NCAND) g_cand[pos] = key;
    }
}

__device__ __forceinline__ bool bt_sw(unsigned long long a, unsigned long long b, bool up)
{
    return up ? (a > b) : (a < b);
}

__global__ __launch_bounds__(1024) void cand_local_kernel()
{
    __shared__ unsigned long long s[4096];
    int base = blockIdx.x * 4096;
    for (int e = threadIdx.x; e < 4096; e += 1024) s[e] = g_cand[base + e];
    __syncthreads();
    for (int k = 2; k <= 4096; k <<= 1)
        for (int j = k >> 1; j > 0; j >>= 1) {
            for (int t = threadIdx.x; t < 2048; t += 1024) {
                int i1 = ((t & ~(j - 1)) << 1) | (t & (j - 1));
                int i2 = i1 + j;
                bool up = (((base + i1) & k) != 0);
                unsigned long long a = s[i1], b = s[i2];
                if (bt_sw(a, b, up)) { s[i1] = b; s[i2] = a; }
            }
            __syncthreads();
        }
    for (int e = threadIdx.x; e < 4096; e += 1024) g_cand[base + e] = s[e];
}

__global__ __launch_bounds__(256) void cand_global_kernel(int k, int j)
{
    int t = blockIdx.x * 256 + threadIdx.x;
    int i1 = ((t & ~(j - 1)) << 1) | (t & (j - 1));
    int i2 = i1 + j;
    bool up = ((i1 & k) != 0);
    unsigned long long a = g_cand[i1], b = g_cand[i2];
    if (bt_sw(a, b, up)) { g_cand[i1] = b; g_cand[i2] = a; }
}

__global__ __launch_bounds__(1024) void cand_fused_kernel(int k)
{
    __shared__ unsigned long long s[4096];
    int base = blockIdx.x * 4096;
    for (int e = threadIdx.x; e < 4096; e += 1024) s[e] = g_cand[base + e];
    __syncthreads();
    for (int j = 2048; j > 0; j >>= 1) {
        for (int t = threadIdx.x; t < 2048; t += 1024) {
            int i1 = ((t & ~(j - 1)) << 1) | (t & (j - 1));
            int i2 = i1 + j;
            bool up = (((base + i1) & k) != 0);
            unsigned long long a = s[i1], b = s[i2];
            if (bt_sw(a, b, up)) { s[i1] = b; s[i2] = a; }
        }
        __syncthreads();
    }
    for (int e = threadIdx.x; e < 4096; e += 1024) g_cand[base + e] = s[e];
}

__global__ void gather_kernel()
{
    int i = blockIdx.x * 256 + threadIdx.x;
    if (i >= PRE_NMS_N) return;
    unsigned idx = ~((unsigned)(g_cand[i] & 0xFFFFFFFFULL));
    g_top_boxes[i] = g_boxes[idx];
}

__global__ __launch_bounds__(64) void nms_mask_kernel()
{
    int rb = blockIdx.y, cb = blockIdx.x;
    if (cb < rb) return;
    __shared__ float4 cbox[64];
    int tid = threadIdx.x;
    int col0 = cb * 64;
    int ccount = min(PRE_NMS_N - col0, 64);
    if (tid < ccount) cbox[tid] = g_top_boxes[col0 + tid];
    __syncthreads();
    int i = rb * 64 + tid;
    if (i >= PRE_NMS_N) return;
    float4 bi = g_top_boxes[i];
    float ai = __fmul_rn(__fadd_rn(__fsub_rn(bi.z, bi.x), 1.0f),
                         __fadd_rn(__fsub_rn(bi.w, bi.y), 1.0f));
    unsigned long long bits = 0ULL;
    for (int c = 0; c < ccount; c++) {
        int j = col0 + c;
        if (j <= i) continue;
        float4 bj = cbox[c];
        float xx1 = fmaxf(bi.x, bj.x), yy1 = fmaxf(bi.y, bj.y);
        float xx2 = fminf(bi.z, bj.z), yy2 = fminf(bi.w, bj.w);
        float iw = fmaxf(0.f, __fadd_rn(__fsub_rn(xx2, xx1), 1.0f));
        float ih = fmaxf(0.f, __fadd_rn(__fsub_rn(yy2, yy1), 1.0f));
        float inter = __fmul_rn(iw, ih);
        float aj = __fmul_rn(__fadd_rn(__fsub_rn(bj.z, bj.x), 1.0f),
                             __fadd_rn(__fsub_rn(bj.w, bj.y), 1.0f));
        float iou = __fdiv_rn(inter, __fsub_rn(__fadd_rn(ai, aj), inter));
        if (iou > 0.7f) bits |= (1ULL << c);
    }
    g_mask[(size_t)i * MASK_W + cb] = bits;
}

__global__ __launch_bounds__(32) void nms_reduce_kernel()
{
    __shared__ int keptlist[POST_NMS_N];
    const unsigned FULL = 0xffffffffu;
    int lane = threadIdx.x;
    unsigned long long remv0 = 0, remv1 = 0, remv2 = 0;
    unsigned long long kb0 = 0, kb1 = 0, kb2 = 0;
    int nkept = 0;

    for (int w = 0; w < MASK_W && nkept < POST_NMS_N; w++) {
        int owner = (w < 32) ? w : ((w < 64) ? w - 32 : w - 64);
        unsigned long long supp;
        if (w < 32)      supp = __shfl_sync(FULL, remv0, owner);
        else if (w < 64) supp = __shfl_sync(FULL, remv1, owner);
        else             supp = __shfl_sync(FULL, remv2, owner);
        unsigned long long live = ~supp;
        if (w == MASK_W - 1) live &= (1ULL << 48) - 1ULL;

        while (live && nkept < POST_NMS_N) {
            int b = __ffsll((long long)live) - 1;
            int i = (w << 6) + b;
            if (lane == 0) keptlist[nkept] = i;
            nkept++;
            if (lane == owner) {
                if (w < 32)      kb0 |= 1ULL << b;
                else if (w < 64) kb1 |= 1ULL << b;
                else             kb2 |= 1ULL << b;
            }
            const unsigned long long* row = g_mask + (size_t)i * MASK_W;
            remv0 |= row[lane];
            remv1 |= row[lane + 32];
            if (lane + 64 < MASK_W) remv2 |= row[lane + 64];
            unsigned long long supp2;
            if (w < 32)      supp2 = __shfl_sync(FULL, remv0, owner);
            else if (w < 64) supp2 = __shfl_sync(FULL, remv1, owner);
            else             supp2 = __shfl_sync(FULL, remv2, owner);
            live &= ~supp2;
            live &= ~(1ULL << b);
        }
    }

    for (int w = 0; w < MASK_W && nkept < POST_NMS_N; w++) {
        int owner = (w < 32) ? w : ((w < 64) ? w - 32 : w - 64);
        unsigned long long kw;
        if (w < 32)      kw = __shfl_sync(FULL, kb0, owner);
        else if (w < 64) kw = __shfl_sync(FULL, kb1, owner);
        else             kw = __shfl_sync(FULL, kb2, owner);
        unsigned long long live = ~kw;
        if (w == MASK_W - 1) live &= (1ULL << 48) - 1ULL;
        while (live && nkept < POST_NMS_N) {
            int b = __ffsll((long long)live) - 1;
            if (lane == 0) keptlist[nkept] = (w << 6) + b;
            nkept++;
            live &= live - 1;
        }
    }
    __syncwarp();
    for (int t = lane; t < POST_NMS_N; t += 32) g_sel[t] = keptlist[t];
}

__global__ void rois_kernel(float* __restrict__ out)
{
    int t = blockIdx.x * 64 + threadIdx.x;
    if (t >= POST_NMS_N) return;
    float4 b = g_top_boxes[g_sel[t]];
    out[t * 5 + 0] = 0.f;
    out[t * 5 + 1] = b.x;
    out[t * 5 + 2] = b.y;
    out[t * 5 + 3] = b.z;
    out[t * 5 + 4] = b.w;
}

extern "C" void kernel_launch(void* const* d_in, const int* in_sizes, int n_in,
                              void* d_out, int out_size)
{
    const float* feature_map = (const float*)d_in[0];
    const float* im_info     = (const float*)d_in[1];
    const float* conv_w      = (const float*)d_in[2];
    const float* conv_b      = (const float*)d_in[3];
    const float* cls_w       = (const float*)d_in[4];
    const float* cls_b       = (const float*)d_in[5];
    const float* bbox_w      = (const float*)d_in[6];
    const float* bbox_b      = (const float*)d_in[7];
    float* out = (float*)d_out;

    cudaFuncSetAttribute(conv_hybrid_kernel,
                         cudaFuncAttributeMaxDynamicSharedMemorySize, SMEM_DYN);

    wtrans_kernel<<<(512 * KTOT + 255) / 256, 256>>>(conv_w);
    wsplit_kernel<<<(512 * KTOT + 255) / 256, 256>>>(conv_w);
    isplit_kernel<<<dim3(NPIX / 32, 16), 256>>>(feature_map);

    conv_hybrid_kernel<<<dim3((NPIX + 127) / 128, 4), 384, SMEM_DYN>>>(feature_map, conv_b);

    zero_sel_kernel<<<(NCAND + 255) / 256, 256>>>();
    head_kernel<<<(NPIX + 63) / 64, 256>>>(cls_w, cls_b, bbox_w, bbox_b);
    decode_kernel<<<(NANCH + 255) / 256, 256>>>(im_info);

    scan1_kernel<<<1, 128>>>();
    hist2_kernel<<<(NANCH + 255) / 256, 256>>>();
    scan2_kernel<<<1, 128>>>();
    compact_kernel<<<(NANCH + 255) / 256, 256>>>();

    cand_local_kernel<<<NCAND / 4096, 1024>>>();
    cand_global_kernel<<<NCAND / 512, 256>>>(NCAND, NCAND / 2);
    cand_fused_kernel<<<NCAND / 4096, 1024>>>(NCAND);

    gather_kernel<<<(PRE_NMS_N + 255) / 256, 256>>>();
    dim3 mgrid(MASK_W, MASK_W);
    nms_mask_kernel<<<mgrid, 64>>>();
    nms_reduce_kernel<<<1, 32>>>();
    rois_kernel<<<(POST_NMS_N + 63) / 64, 64>>>(out);
}

// round 13
// speedup vs baseline: 2.8556x; 2.8556x over previous
#include <cuda_runtime.h>
#include <math.h>
#include <stdint.h>

#define W_ 152
#define H_ 100
#define NPIX 15200
#define NANCH 136800
#define NCAND 8192
#define NHIST 4096
#define PRE_NMS_N 6000
#define POST_NMS_N 300
#define MASK_W 94
#define NTILE 3800          // 50 x 76 winograd tiles
#define NTP 3840            // padded tile count (x128)
#define PLANE (512 * NTP)   // elements per winograd plane

__device__ float g_U[16 * 512 * 512];
__device__ float g_V[16 * PLANE];
__device__ float g_M[16 * PLANE];
__device__ float g_x[512 * NPIX];
__device__ float g_head[54 * NPIX];
__device__ float4 g_boxes[NANCH];
__device__ unsigned long long g_keys[NANCH];
__device__ unsigned long long g_cand[NCAND];
__device__ int g_hist1[NHIST];
__device__ int g_hist2[NHIST];
__device__ int g_b1;
__device__ int g_above1;
__device__ unsigned g_T24;
__device__ int g_count;
__device__ float4 g_top_boxes[PRE_NMS_N];
__device__ unsigned long long g_mask[(size_t)PRE_NMS_N * MASK_W];
__device__ int g_sel[POST_NMS_N];

__constant__ float c_anchors[9][4] = {
    {-84.f,-40.f,99.f,55.f},{-176.f,-88.f,191.f,103.f},{-360.f,-184.f,375.f,199.f},
    {-56.f,-56.f,71.f,71.f},{-120.f,-120.f,135.f,135.f},{-248.f,-248.f,263.f,263.f},
    {-36.f,-80.f,51.f,95.f},{-80.f,-168.f,95.f,183.f},{-168.f,-344.f,183.f,359.f}
};

// ---- weight transform: U = G g G^T  (correlation form, exact halves)
__global__ __launch_bounds__(256) void wino_w_kernel(const float* __restrict__ wgt)
{
    int idx = blockIdx.x * 256 + threadIdx.x;
    if (idx >= 512 * 512) return;
    const float* g = wgt + (size_t)idx * 9;
    float t[4][3];
#pragma unroll
    for (int c = 0; c < 3; c++) {
        float g0 = g[c], g1 = g[3 + c], g2 = g[6 + c];
        t[0][c] = g0;
        t[1][c] = __fmul_rn(0.5f, __fadd_rn(__fadd_rn(g0, g1), g2));
        t[2][c] = __fmul_rn(0.5f, __fadd_rn(__fsub_rn(g0, g1), g2));
        t[3][c] = g2;
    }
#pragma unroll
    for (int i = 0; i < 4; i++) {
        float u0 = t[i][0];
        float u1 = __fmul_rn(0.5f, __fadd_rn(__fadd_rn(t[i][0], t[i][1]), t[i][2]));
        float u2 = __fmul_rn(0.5f, __fadd_rn(__fsub_rn(t[i][0], t[i][1]), t[i][2]));
        float u3 = t[i][2];
        g_U[(i * 4 + 0) * 262144 + idx] = u0;
        g_U[(i * 4 + 1) * 262144 + idx] = u1;
        g_U[(i * 4 + 2) * 262144 + idx] = u2;
        g_U[(i * 4 + 3) * 262144 + idx] = u3;
    }
}

// ---- input transform: V = B^T d B per (ic, tile)
__global__ __launch_bounds__(256) void wino_in_kernel(const float* __restrict__ in)
{
    int idx = blockIdx.x * 256 + threadIdx.x;
    if (idx >= 512 * NTILE) return;
    int ic = idx / NTILE, tile = idx - ic * NTILE;
    int ty = tile / 76, tx = tile - ty * 76;
    int r0 = 2 * ty - 1, c0 = 2 * tx - 1;
    const float* src = in + (size_t)ic * NPIX;
    float d[4][4];
#pragma unroll
    for (int r = 0; r < 4; r++) {
        int rr = r0 + r;
        bool rv = (rr >= 0) && (rr < H_);
#pragma unroll
        for (int c = 0; c < 4; c++) {
            int cc = c0 + c;
            d[r][c] = (rv && cc >= 0 && cc < W_) ? src[rr * W_ + cc] : 0.f;
        }
    }
    float t[4][4];
#pragma unroll
    for (int c = 0; c < 4; c++) {
        t[0][c] = __fsub_rn(d[0][c], d[2][c]);
        t[1][c] = __fadd_rn(d[1][c], d[2][c]);
        t[2][c] = __fsub_rn(d[2][c], d[1][c]);
        t[3][c] = __fsub_rn(d[1][c], d[3][c]);
    }
    size_t base = (size_t)ic * NTP + tile;
#pragma unroll
    for (int i = 0; i < 4; i++) {
        g_V[(size_t)(i * 4 + 0) * PLANE + base] = __fsub_rn(t[i][0], t[i][2]);
        g_V[(size_t)(i * 4 + 1) * PLANE + base] = __fadd_rn(t[i][1], t[i][2]);
        g_V[(size_t)(i * 4 + 2) * PLANE + base] = __fsub_rn(t[i][2], t[i][1]);
        g_V[(size_t)(i * 4 + 3) * PLANE + base] = __fsub_rn(t[i][1], t[i][3]);
    }
}

// ---- 16 batched GEMMs: M_j[512][3840] = U_j[512][512] x V_j[512][3840]
// R3-proven FFMA2 microkernel: BM=128, BN=128, BK=8, 128 thr, 8(m) x 16(n)/thread
__global__ __launch_bounds__(128) void wino_gemm_kernel()
{
    __shared__ float As[2][8][132];
    __shared__ float Bs[2][8][132];
    const int tid = threadIdx.x;
    const int tx = tid & 7, ty = tid >> 3;
    const int bn = blockIdx.x * 128;
    const int bm = blockIdx.y * 128;
    const int j = blockIdx.z;
    const float* Up = g_U + (size_t)j * 262144 + (size_t)(bm + tid) * 512;
    const float* Vp = g_V + (size_t)j * PLANE;
    float* Mp = g_M + (size_t)j * PLANE;

    unsigned long long acc[8][8];
#pragma unroll
    for (int i = 0; i < 8; i++)
#pragma unroll
        for (int q = 0; q < 8; q++) acc[i][q] = 0ULL;

    float Areg[8], Breg[8];
    auto loadTile = [&](int it, float* ar, float* br) {
        int k0 = it * 8;
        float4 a0 = *reinterpret_cast<const float4*>(Up + k0);
        float4 a1 = *reinterpret_cast<const float4*>(Up + k0 + 4);
        ar[0]=a0.x; ar[1]=a0.y; ar[2]=a0.z; ar[3]=a0.w;
        ar[4]=a1.x; ar[5]=a1.y; ar[6]=a1.z; ar[7]=a1.w;
        const float* vcol = Vp + (size_t)k0 * NTP + bn + tid;
#pragma unroll
        for (int r = 0; r < 8; r++)
            br[r] = __ldg(vcol + (size_t)r * NTP);
    };
    auto storeTile = [&](int buf, const float* ar, const float* br) {
#pragma unroll
        for (int kk = 0; kk < 8; kk++) As[buf][kk][tid] = ar[kk];
#pragma unroll
        for (int kk = 0; kk < 8; kk++) Bs[buf][kk][tid] = br[kk];
    };

    loadTile(0, Areg, Breg);
    storeTile(0, Areg, Breg);
    __syncthreads();

    int cur = 0;
    const int NIT = 64;
    for (int it = 0; it < NIT; it++) {
        bool more = (it + 1 < NIT);
        if (more) loadTile(it + 1, Areg, Breg);

#pragma unroll
        for (int kk = 0; kk < 8; kk++) {
            const float4* arow = reinterpret_cast<const float4*>(&As[cur][kk][0]);
            const ulonglong2* brow = reinterpret_cast<const ulonglong2*>(&Bs[cur][kk][0]);
            unsigned long long b2[8];
#pragma unroll
            for (int q = 0; q < 4; q++) {
                ulonglong2 t = brow[tx + q * 8];
                b2[2 * q] = t.x;
                b2[2 * q + 1] = t.y;
            }
            float4 a0 = arow[ty];
            float4 a1 = arow[ty + 16];
            float av[8];
            av[0]=a0.x; av[1]=a0.y; av[2]=a0.z; av[3]=a0.w;
            av[4]=a1.x; av[5]=a1.y; av[6]=a1.z; av[7]=a1.w;
            unsigned long long a2[8];
#pragma unroll
            for (int s = 0; s < 8; s++)
                asm("mov.b64 %0, {%1, %1};" : "=l"(a2[s]) : "f"(av[s]));
#pragma unroll
            for (int s = 0; s < 8; s++)
#pragma unroll
                for (int q = 0; q < 8; q++)
                    asm("fma.rn.f32x2 %0, %1, %2, %0;"
                        : "+l"(acc[s][q]) : "l"(a2[s]), "l"(b2[q]));
        }

        if (more) {
            storeTile(cur ^ 1, Areg, Breg);
            __syncthreads();
            cur ^= 1;
        }
    }

#pragma unroll
    for (int r = 0; r < 2; r++)
#pragma unroll
        for (int s = 0; s < 4; s++) {
            int m = bm + r * 64 + ty * 4 + s;
#pragma unroll
            for (int q = 0; q < 4; q++)
#pragma unroll
                for (int t = 0; t < 2; t++) {
                    int n = bn + q * 32 + tx * 4 + t * 2;
                    unsigned long long v = acc[r * 4 + s][q * 2 + t];
                    float lo, hi;
                    asm("mov.b64 {%0, %1}, %2;" : "=f"(lo), "=f"(hi) : "l"(v));
                    *reinterpret_cast<float2*>(&Mp[(size_t)m * NTP + n]) =
                        make_float2(lo, hi);
                }
        }
}

// ---- output transform: Y = A^T M A + bias, relu
__global__ __launch_bounds__(256) void wino_out_kernel(const float* __restrict__ bias)
{
    int idx = blockIdx.x * 256 + threadIdx.x;
    if (idx >= 512 * NTILE) return;
    int oc = idx / NTILE, tile = idx - oc * NTILE;
    int ty = tile / 76, tx = tile - ty * 76;
    size_t base = (size_t)oc * NTP + tile;
    float m[16];
#pragma unroll
    for (int j = 0; j < 16; j++)
        m[j] = g_M[(size_t)j * PLANE + base];
    float t0[4], t1[4];
#pragma unroll
    for (int c = 0; c < 4; c++) {
        t0[c] = __fadd_rn(__fadd_rn(m[c], m[4 + c]), m[8 + c]);
        t1[c] = __fsub_rn(__fsub_rn(m[4 + c], m[8 + c]), m[12 + c]);
    }
    float bv = bias[oc];
    float y00 = __fadd_rn(__fadd_rn(t0[0], t0[1]), t0[2]);
    float y01 = __fsub_rn(__fsub_rn(t0[1], t0[2]), t0[3]);
    float y10 = __fadd_rn(__fadd_rn(t1[0], t1[1]), t1[2]);
    float y11 = __fsub_rn(__fsub_rn(t1[1], t1[2]), t1[3]);
    float* dst = g_x + (size_t)oc * NPIX + (2 * ty) * W_ + 2 * tx;
    dst[0]      = fmaxf(__fadd_rn(y00, bv), 0.f);
    dst[1]      = fmaxf(__fadd_rn(y01, bv), 0.f);
    dst[W_]     = fmaxf(__fadd_rn(y10, bv), 0.f);
    dst[W_ + 1] = fmaxf(__fadd_rn(y11, bv), 0.f);
}

// ---- heads: BN=64 (grid 238)
__global__ __launch_bounds__(256) void head_kernel(
    const float* __restrict__ cls_w, const float* __restrict__ cls_b,
    const float* __restrict__ bbox_w, const float* __restrict__ bbox_b)
{
    __shared__ float As[16][68];
    __shared__ float Bs[16][68];
    const int tid = threadIdx.x;
    const int bn = blockIdx.x * 64;
    const int tx = tid & 15, ty = tid >> 4;

    float acc[4][4];
#pragma unroll
    for (int i = 0; i < 4; i++)
#pragma unroll
        for (int j = 0; j < 4; j++) acc[i][j] = 0.f;

    for (int k0 = 0; k0 < 512; k0 += 16) {
        {
            int m = tid >> 2, kq = (tid & 3) << 2;
            float4 v = make_float4(0.f, 0.f, 0.f, 0.f);
            if (m < 18) v = *reinterpret_cast<const float4*>(cls_w + (size_t)m * 512 + k0 + kq);
            else if (m < 54) v = *reinterpret_cast<const float4*>(bbox_w + (size_t)(m - 18) * 512 + k0 + kq);
            As[kq + 0][m] = v.x; As[kq + 1][m] = v.y; As[kq + 2][m] = v.z; As[kq + 3][m] = v.w;
        }
#pragma unroll
        for (int r = 0; r < 4; r++) {
            int e = r * 256 + tid, kk = e >> 6, nn = e & 63, p = bn + nn;
            Bs[kk][nn] = (p < NPIX) ? g_x[(size_t)(k0 + kk) * NPIX + p] : 0.f;
        }
        __syncthreads();
#pragma unroll
        for (int kk = 0; kk < 16; kk++) {
            float a[4], b[4];
            float4 a0 = *reinterpret_cast<float4*>(&As[kk][ty * 4]);
            float4 b0 = *reinterpret_cast<float4*>(&Bs[kk][tx * 4]);
            a[0]=a0.x; a[1]=a0.y; a[2]=a0.z; a[3]=a0.w;
            b[0]=b0.x; b[1]=b0.y; b[2]=b0.z; b[3]=b0.w;
#pragma unroll
            for (int i = 0; i < 4; i++)
#pragma unroll
                for (int j = 0; j < 4; j++)
                    acc[i][j] = __fmaf_rn(a[i], b[j], acc[i][j]);
        }
        __syncthreads();
    }
#pragma unroll
    for (int i = 0; i < 4; i++) {
        int m = ty * 4 + i;
        if (m >= 54) continue;
        float bv = (m < 18) ? cls_b[m] : bbox_b[m - 18];
#pragma unroll
        for (int j = 0; j < 4; j++) {
            int n = bn + tx * 4 + j;
            if (n < NPIX) g_head[(size_t)m * NPIX + n] = __fadd_rn(acc[i][j], bv);
        }
    }
}

__global__ void zero_sel_kernel()
{
    int idx = blockIdx.x * 256 + threadIdx.x;
    if (idx < NCAND) g_cand[idx] = 0ULL;
    if (idx < NHIST) { g_hist1[idx] = 0; g_hist2[idx] = 0; }
    if (idx == 0) g_count = 0;
}

__global__ void decode_kernel(const float* __restrict__ iminfo)
{
    int idx = blockIdx.x * 256 + threadIdx.x;
    if (idx >= NANCH) return;
    int a = idx % 9, p = idx / 9, h = p / W_, w = p - h * W_;

    float s0 = g_head[(size_t)a * NPIX + p];
    float s1 = g_head[(size_t)(9 + a) * NPIX + p];
    float mx = fmaxf(s0, s1);
    float e0 = (float)exp((double)__fsub_rn(s0, mx));
    float e1 = (float)exp((double)__fsub_rn(s1, mx));
    float fg = __fdiv_rn(e1, __fadd_rn(e0, e1));

    float d0 = g_head[(size_t)(18 + a * 4 + 0) * NPIX + p];
    float d1 = g_head[(size_t)(18 + a * 4 + 1) * NPIX + p];
    float d2 = g_head[(size_t)(18 + a * 4 + 2) * NPIX + p];
    float d3 = g_head[(size_t)(18 + a * 4 + 3) * NPIX + p];

    float sx = (float)(w * 16), sy = (float)(h * 16);
    float x1a = c_anchors[a][0] + sx, y1a = c_anchors[a][1] + sy;
    float x2a = c_anchors[a][2] + sx, y2a = c_anchors[a][3] + sy;
    float aw = __fadd_rn(__fsub_rn(x2a, x1a), 1.0f);
    float ah = __fadd_rn(__fsub_rn(y2a, y1a), 1.0f);
    float ax = __fadd_rn(x1a, __fmul_rn(0.5f, aw));
    float ay = __fadd_rn(y1a, __fmul_rn(0.5f, ah));

    float px = __fadd_rn(__fmul_rn(d0, aw), ax);
    float py = __fadd_rn(__fmul_rn(d1, ah), ay);
    float pwv = __fmul_rn((float)exp((double)d2), aw);
    float phv = __fmul_rn((float)exp((double)d3), ah);

    float x1 = __fsub_rn(px, __fmul_rn(0.5f, pwv));
    float y1 = __fsub_rn(py, __fmul_rn(0.5f, phv));
    float x2 = __fadd_rn(px, __fmul_rn(0.5f, pwv));
    float y2 = __fadd_rn(py, __fmul_rn(0.5f, phv));

    float hiX = __fsub_rn(iminfo[1], 1.0f);
    float hiY = __fsub_rn(iminfo[0], 1.0f);
    x1 = fminf(fmaxf(x1, 0.f), hiX);
    y1 = fminf(fmaxf(y1, 0.f), hiY);
    x2 = fminf(fmaxf(x2, 0.f), hiX);
    y2 = fminf(fmaxf(y2, 0.f), hiY);

    float ws = __fadd_rn(__fsub_rn(x2, x1), 1.0f);
    float hs = __fadd_rn(__fsub_rn(y2, y1), 1.0f);
    float msz = __fmul_rn(16.0f, iminfo[2]);
    bool valid = (ws >= msz) && (hs >= msz);
    float score = valid ? fg : -1000000000.0f;

    unsigned u = __float_as_uint(score);
    u = (u & 0x80000000u) ? ~u : (u | 0x80000000u);
    g_keys[idx] = ((unsigned long long)u << 32) | (unsigned)(~(unsigned)idx);
    g_boxes[idx] = make_float4(x1, y1, x2, y2);
    atomicAdd(&g_hist1[u >> 20], 1);
}

__global__ __launch_bounds__(128) void scan1_kernel()
{
    __shared__ int part[128];
    int t = threadIdx.x, s = 0;
#pragma unroll
    for (int q = 0; q < 32; q++) s += g_hist1[t * 32 + q];
    part[t] = s;
    __syncthreads();
    if (t == 0) {
        int cum = 0, seg = 0;
        for (int pp = 127; pp >= 0; pp--) {
            if (cum + part[pp] >= PRE_NMS_N) { seg = pp; break; }
            cum += part[pp];
            if (pp == 0) seg = 0;
        }
        int b = seg * 32 + 31;
        for (; b >= seg * 32; b--) {
            int c = g_hist1[b];
            if (cum + c >= PRE_NMS_N) break;
            cum += c;
        }
        if (b < seg * 32) b = seg * 32;
        g_b1 = b; g_above1 = cum;
    }
}

__global__ void hist2_kernel()
{
    int idx = blockIdx.x * 256 + threadIdx.x;
    if (idx >= NANCH) return;
    unsigned u = (unsigned)(g_keys[idx] >> 32);
    if ((int)(u >> 20) == g_b1) atomicAdd(&g_hist2[(u >> 8) & 0xFFF], 1);
}

__global__ __launch_bounds__(128) void scan2_kernel()
{
    __shared__ int part[128];
    int t = threadIdx.x, s = 0;
#pragma unroll
    for (int q = 0; q < 32; q++) s += g_hist2[t * 32 + q];
    part[t] = s;
    __syncthreads();
    if (t == 0) {
        int cum = g_above1, seg = 0;
        for (int pp = 127; pp >= 0; pp--) {
            if (cum + part[pp] >= PRE_NMS_N) { seg = pp; break; }
            cum += part[pp];
            if (pp == 0) seg = 0;
        }
        int b = seg * 32 + 31;
        for (; b >= seg * 32; b--) {
            int c = g_hist2[b];
            if (cum + c >= PRE_NMS_N) break;
            cum += c;
        }
        if (b < seg * 32) b = seg * 32;
        g_T24 = ((unsigned)g_b1 << 12) | (unsigned)b;
    }
}

__global__ void compact_kernel()
{
    int idx = blockIdx.x * 256 + threadIdx.x;
    if (idx >= NANCH) return;
    unsigned long long key = g_keys[idx];
    unsigned u = (unsigned)(key >> 32);
    if ((u >> 8) >= g_T24) {
        int pos = atomicAdd(&g_count, 1);
        if (pos < NCAND) g_cand[pos] = key;
    }
}

__device__ __forceinline__ bool bt_sw(unsigned long long a, unsigned long long b, bool up)
{
    return up ? (a > b) : (a < b);
}

__global__ __launch_bounds__(1024) void cand_local_kernel()
{
    __shared__ unsigned long long s[4096];
    int base = blockIdx.x * 4096;
    for (int e = threadIdx.x; e < 4096; e += 1024) s[e] = g_cand[base + e];
    __syncthreads();
    for (int k = 2; k <= 4096; k <<= 1)
        for (int j = k >> 1; j > 0; j >>= 1) {
            for (int t = threadIdx.x; t < 2048; t += 1024) {
                int i1 = ((t & ~(j - 1)) << 1) | (t & (j - 1));
                int i2 = i1 + j;
                bool up = (((base + i1) & k) != 0);
                unsigned long long a = s[i1], b = s[i2];
                if (bt_sw(a, b, up)) { s[i1] = b; s[i2] = a; }
            }
            __syncthreads();
        }
    for (int e = threadIdx.x; e < 4096; e += 1024) g_cand[base + e] = s[e];
}

__global__ __launch_bounds__(256) void cand_global_kernel(int k, int j)
{
    int t = blockIdx.x * 256 + threadIdx.x;
    int i1 = ((t & ~(j - 1)) << 1) | (t & (j - 1));
    int i2 = i1 + j;
    bool up = ((i1 & k) != 0);
    unsigned long long a = g_cand[i1], b = g_cand[i2];
    if (bt_sw(a, b, up)) { g_cand[i1] = b; g_cand[i2] = a; }
}

__global__ __launch_bounds__(1024) void cand_fused_kernel(int k)
{
    __shared__ unsigned long long s[4096];
    int base = blockIdx.x * 4096;
    for (int e = threadIdx.x; e < 4096; e += 1024) s[e] = g_cand[base + e];
    __syncthreads();
    for (int j = 2048; j > 0; j >>= 1) {
        for (int t = threadIdx.x; t < 2048; t += 1024) {
            int i1 = ((t & ~(j - 1)) << 1) | (t & (j - 1));
            int i2 = i1 + j;
            bool up = (((base + i1) & k) != 0);
            unsigned long long a = s[i1], b = s[i2];
            if (bt_sw(a, b, up)) { s[i1] = b; s[i2] = a; }
        }
        __syncthreads();
    }
    for (int e = threadIdx.x; e < 4096; e += 1024) g_cand[base + e] = s[e];
}

__global__ void gather_kernel()
{
    int i = blockIdx.x * 256 + threadIdx.x;
    if (i >= PRE_NMS_N) return;
    unsigned idx = ~((unsigned)(g_cand[i] & 0xFFFFFFFFULL));
    g_top_boxes[i] = g_boxes[idx];
}

__global__ __launch_bounds__(64) void nms_mask_kernel()
{
    int rb = blockIdx.y, cb = blockIdx.x;
    if (cb < rb) return;
    __shared__ float4 cbox[64];
    int tid = threadIdx.x;
    int col0 = cb * 64;
    int ccount = min(PRE_NMS_N - col0, 64);
    if (tid < ccount) cbox[tid] = g_top_boxes[col0 + tid];
    __syncthreads();
    int i = rb * 64 + tid;
    if (i >= PRE_NMS_N) return;
    float4 bi = g_top_boxes[i];
    float ai = __fmul_rn(__fadd_rn(__fsub_rn(bi.z, bi.x), 1.0f),
                         __fadd_rn(__fsub_rn(bi.w, bi.y), 1.0f));
    unsigned long long bits = 0ULL;
    for (int c = 0; c < ccount; c++) {
        int j = col0 + c;
        if (j <= i) continue;
        float4 bj = cbox[c];
        float xx1 = fmaxf(bi.x, bj.x), yy1 = fmaxf(bi.y, bj.y);
        float xx2 = fminf(bi.z, bj.z), yy2 = fminf(bi.w, bj.w);
        float iw = fmaxf(0.f, __fadd_rn(__fsub_rn(xx2, xx1), 1.0f));
        float ih = fmaxf(0.f, __fadd_rn(__fsub_rn(yy2, yy1), 1.0f));
        float inter = __fmul_rn(iw, ih);
        float aj = __fmul_rn(__fadd_rn(__fsub_rn(bj.z, bj.x), 1.0f),
                             __fadd_rn(__fsub_rn(bj.w, bj.y), 1.0f));
        float iou = __fdiv_rn(inter, __fsub_rn(__fadd_rn(ai, aj), inter));
        if (iou > 0.7f) bits |= (1ULL << c);
    }
    g_mask[(size_t)i * MASK_W + cb] = bits;
}

__global__ __launch_bounds__(32) void nms_reduce_kernel()
{
    __shared__ int keptlist[POST_NMS_N];
    const unsigned FULL = 0xffffffffu;
    int lane = threadIdx.x;
    unsigned long long remv0 = 0, remv1 = 0, remv2 = 0;
    unsigned long long kb0 = 0, kb1 = 0, kb2 = 0;
    int nkept = 0;

    for (int w = 0; w < MASK_W && nkept < POST_NMS_N; w++) {
        int owner = (w < 32) ? w : ((w < 64) ? w - 32 : w - 64);
        unsigned long long supp;
        if (w < 32)      supp = __shfl_sync(FULL, remv0, owner);
        else if (w < 64) supp = __shfl_sync(FULL, remv1, owner);
        else             supp = __shfl_sync(FULL, remv2, owner);
        unsigned long long live = ~supp;
        if (w == MASK_W - 1) live &= (1ULL << 48) - 1ULL;

        while (live && nkept < POST_NMS_N) {
            int b = __ffsll((long long)live) - 1;
            int i = (w << 6) + b;
            if (lane == 0) keptlist[nkept] = i;
            nkept++;
            if (lane == owner) {
                if (w < 32)      kb0 |= 1ULL << b;
                else if (w < 64) kb1 |= 1ULL << b;
                else             kb2 |= 1ULL << b;
            }
            const unsigned long long* row = g_mask + (size_t)i * MASK_W;
            remv0 |= row[lane];
            remv1 |= row[lane + 32];
            if (lane + 64 < MASK_W) remv2 |= row[lane + 64];
            unsigned long long supp2;
            if (w < 32)      supp2 = __shfl_sync(FULL, remv0, owner);
            else if (w < 64) supp2 = __shfl_sync(FULL, remv1, owner);
            else             supp2 = __shfl_sync(FULL, remv2, owner);
            live &= ~supp2;
            live &= ~(1ULL << b);
        }
    }

    for (int w = 0; w < MASK_W && nkept < POST_NMS_N; w++) {
        int owner = (w < 32) ? w : ((w < 64) ? w - 32 : w - 64);
        unsigned long long kw;
        if (w < 32)      kw = __shfl_sync(FULL, kb0, owner);
        else if (w < 64) kw = __shfl_sync(FULL, kb1, owner);
        else             kw = __shfl_sync(FULL, kb2, owner);
        unsigned long long live = ~kw;
        if (w == MASK_W - 1) live &= (1ULL << 48) - 1ULL;
        while (live && nkept < POST_NMS_N) {
            int b = __ffsll((long long)live) - 1;
            if (lane == 0) keptlist[nkept] = (w << 6) + b;
            nkept++;
            live &= live - 1;
        }
    }
    __syncwarp();
    for (int t = lane; t < POST_NMS_N; t += 32) g_sel[t] = keptlist[t];
}

__global__ void rois_kernel(float* __restrict__ out)
{
    int t = blockIdx.x * 64 + threadIdx.x;
    if (t >= POST_NMS_N) return;
    float4 b = g_top_boxes[g_sel[t]];
    out[t * 5 + 0] = 0.f;
    out[t * 5 + 1] = b.x;
    out[t * 5 + 2] = b.y;
    out[t * 5 + 3] = b.z;
    out[t * 5 + 4] = b.w;
}

extern "C" void kernel_launch(void* const* d_in, const int* in_sizes, int n_in,
                              void* d_out, int out_size)
{
    const float* feature_map = (const float*)d_in[0];
    const float* im_info     = (const float*)d_in[1];
    const float* conv_w      = (const float*)d_in[2];
    const float* conv_b      = (const float*)d_in[3];
    const float* cls_w       = (const float*)d_in[4];
    const float* cls_b       = (const float*)d_in[5];
    const float* bbox_w      = (const float*)d_in[6];
    const float* bbox_b      = (const float*)d_in[7];
    float* out = (float*)d_out;

    wino_w_kernel<<<(512 * 512 + 255) / 256, 256>>>(conv_w);
    wino_in_kernel<<<(512 * NTILE + 255) / 256, 256>>>(feature_map);
    wino_gemm_kernel<<<dim3(NTP / 128, 4, 16), 128>>>();
    wino_out_kernel<<<(512 * NTILE + 255) / 256, 256>>>(conv_b);

    zero_sel_kernel<<<(NCAND + 255) / 256, 256>>>();
    head_kernel<<<(NPIX + 63) / 64, 256>>>(cls_w, cls_b, bbox_w, bbox_b);
    decode_kernel<<<(NANCH + 255) / 256, 256>>>(im_info);

    scan1_kernel<<<1, 128>>>();
    hist2_kernel<<<(NANCH + 255) / 256, 256>>>();
    scan2_kernel<<<1, 128>>>();
    compact_kernel<<<(NANCH + 255) / 256, 256>>>();

    cand_local_kernel<<<NCAND / 4096, 1024>>>();
    cand_global_kernel<<<NCAND / 512, 256>>>(NCAND, NCAND / 2);
    cand_fused_kernel<<<NCAND / 4096, 1024>>>(NCAND);

    gather_kernel<<<(PRE_NMS_N + 255) / 256, 256>>>();
    dim3 mgrid(MASK_W, MASK_W);
    nms_mask_kernel<<<mgrid, 64>>>();
    nms_reduce_kernel<<<1, 32>>>();
    rois_kernel<<<(POST_NMS_N + 63) / 64, 64>>>(out);
}